// round 15
// baseline (speedup 1.0000x reference)
#include <cuda_runtime.h>
#include <cstdint>
#include <math.h>

// ===========================================================================
// WanCrossAttention  (B=1, L=8192, S=512, C=2048, CTX=4096, H=16, D=128)
// Round-15: TF32 pipeline; tf_gemm templatized on per-warp M tiles (WMT).
//   KV projection -> WMT=2 (64x128 CTA tile, 256 CTAs, 2 CTAs/SM real).
//   ncu R14: KV launch stuck at occ=12.5% because grid=128 < SM count.
// Arithmetic bit-identical to rounds 9-14.
// ===========================================================================

#define L_Q   8192
#define S_KV  512
#define C_DIM 2048
#define CTXD  4096
#define NH    16
#define HD    128

// tf32 GEMM tiling: TK=32 fp32, 3-stage cp.async pipeline
#define RS3   36                     // smem row stride (words): 32 + 4 pad
#define RS3B  144
#define BT3   (128 * RS3B)           // B tile bytes (N=128 always)
// per-WMT A tile: WMT*32 rows * RS3B
#define SMEMSZ(WMT) (3 * ((WMT) * 32 * RS3B + BT3))
// WMT=4: 110592 B (2 CTAs/SM), WMT=2: 82944 B (2 CTAs/SM)

// attn_fused smem layout (unchanged)
#define QRS    132
#define AF_QW  (64 * QRS)
#define AF_KW  (128 * QRS)
#define AF_VW  (128 * 68)
#define AF_PO  17408
#define AF_PRS 516
#define AF_RED 50432
#define AF_SMW 51456
#define AF_SMB (AF_SMW * 4)          // 205824 B

// ---------------- scratch ---------------------------------------------------
__device__ float g_wqt[C_DIM * C_DIM];
__device__ float g_wkvt[2 * C_DIM * CTXD];
__device__ float g_wot[C_DIM * C_DIM];
__device__ float g_qf[L_Q * C_DIM];
__device__ float g_kvf[2 * S_KV * C_DIM];
__device__ float g_vt[C_DIM * S_KV];
__device__ float g_atf[L_Q * C_DIM];
__device__ float g_bkv[2 * C_DIM];

// ---------------- asm helpers ----------------------------------------------
__device__ __forceinline__ uint32_t smem_u32(const void* p) {
    uint32_t a;
    asm("{ .reg .u64 t; cvta.to.shared.u64 t, %1; cvt.u32.u64 %0, t; }"
        : "=r"(a) : "l"(p));
    return a;
}
__device__ __forceinline__ float tf32r(float x) {
    uint32_t o;
    asm("cvt.rna.tf32.f32 %0, %1;" : "=r"(o) : "f"(x));
    return __uint_as_float(o);
}
__device__ __forceinline__ uint32_t tf32rb(uint32_t x) {
    uint32_t o;
    asm("cvt.rna.tf32.f32 %0, %1;" : "=r"(o) : "f"(__uint_as_float(x)));
    return o;
}
__device__ __forceinline__ void ldsm_x4(uint32_t* r, uint32_t addr) {
    asm volatile("ldmatrix.sync.aligned.m8n8.x4.shared.b16 {%0,%1,%2,%3}, [%4];"
                 : "=r"(r[0]), "=r"(r[1]), "=r"(r[2]), "=r"(r[3]) : "r"(addr));
}
__device__ __forceinline__ void mma_tf32(float* c, uint32_t a0, uint32_t a1,
                                         uint32_t a2, uint32_t a3,
                                         uint32_t b0, uint32_t b1) {
    asm volatile(
        "mma.sync.aligned.m16n8k8.row.col.f32.tf32.tf32.f32 "
        "{%0,%1,%2,%3}, {%4,%5,%6,%7}, {%8,%9}, {%0,%1,%2,%3};"
        : "+f"(c[0]), "+f"(c[1]), "+f"(c[2]), "+f"(c[3])
        : "r"(a0), "r"(a1), "r"(a2), "r"(a3), "r"(b0), "r"(b1));
}
#define CP_ASYNC16(dst, src) \
    asm volatile("cp.async.cg.shared.global [%0], [%1], 16;" :: "r"(dst), "l"(src))
#define CP_COMMIT() asm volatile("cp.async.commit_group;" ::: "memory")
#define CP_WAITG(n) asm volatile("cp.async.wait_group %0;" :: "n"(n) : "memory")

// ---------------------------------------------------------------------------
// TF32 GEMM, K-chunk 32, 3-stage pipeline, 2 CTAs/SM.
// WMT = m16 tiles per warp (4 -> CTA 128xN, 2 -> CTA 64xN). N tile = 128.
// K % 32 == 0, K/32 >= 2.
// ---------------------------------------------------------------------------
template <int BIASMODE, int ROUND, int RNDA, int WMT>
__global__ __launch_bounds__(256, 2)
void tf_gemm(const float* __restrict__ A, int lda, long sA,
             const float* __restrict__ B, int ldb, long sB,
             const float* __restrict__ bias, long sBias,
             float* __restrict__ C, int ldc, long sC, int K)
{
    constexpr int CM   = WMT * 32;            // CTA rows
    constexpr uint32_t ATB = (uint32_t)CM * RS3B;       // A tile bytes
    constexpr uint32_t STGB_ = ATB + BT3;               // stage bytes
    constexpr int NA = CM / 32;               // A loader iterations (chunks/256)

    extern __shared__ char smem[];
    const uint32_t sb = smem_u32(smem);
    const int tid = threadIdx.x, wid = tid >> 5, lid = tid & 31;
    const int m0 = blockIdx.y * CM, n0 = blockIdx.x * 128;

    const float* Ab = A + (long)blockIdx.z * sA + (long)m0 * lda;
    const float* Bb = B + (long)blockIdx.z * sB + (long)n0 * ldb;

    // loader: A: CM*8 chunks, B: 1024 chunks per stage
    uint32_t goffA[NA], soA[NA], goffB[4], soB[4];
#pragma unroll
    for (int i = 0; i < NA; ++i) {
        const int idx = i * 256 + tid;
        const int row = (idx >> 3) & (CM - 1);
        const int ch  = idx & 7;
        goffA[i] = (uint32_t)(row * lda + ch * 4);
        soA[i] = (uint32_t)(row * RS3B + ch * 16);
    }
#pragma unroll
    for (int i = 0; i < 4; ++i) {
        const int idx = i * 256 + tid;
        const int row = (idx >> 3) & 127;
        const int ch  = idx & 7;
        goffB[i] = (uint32_t)(row * ldb + ch * 4);
        soB[i] = (uint32_t)(ATB + row * RS3B + ch * 16);
    }

#define ISSUE_STAGE(stage, kidx) do {                                       \
        const uint32_t _db = sb + (uint32_t)(stage) * STGB_;                \
        const uint32_t _go = (uint32_t)(kidx) * 32;                         \
        _Pragma("unroll")                                                   \
        for (int _i = 0; _i < NA; ++_i)                                     \
            CP_ASYNC16(_db + soA[_i], Ab + goffA[_i] + _go);                \
        _Pragma("unroll")                                                   \
        for (int _i = 0; _i < 4; ++_i)                                      \
            CP_ASYNC16(_db + soB[_i], Bb + goffB[_i] + _go);                \
    } while (0)

    // ldmatrix thread offsets (words within a stage)
    const int lm = lid >> 3, lr8 = lid & 7;
    const int wm = wid >> 2, wn = wid & 3;
    const uint32_t fA = (uint32_t)((wm * (16 * WMT) + lr8 + 8 * (lm & 1)) * RS3
                                   + 4 * (lm >> 1));
    const uint32_t fB = (uint32_t)(ATB / 4 + (wn * 32 + lr8 + 8 * (lm >> 1)) * RS3
                                   + 4 * (lm & 1));

    float acc[WMT][4][4];
#pragma unroll
    for (int i = 0; i < WMT; ++i)
#pragma unroll
        for (int j = 0; j < 4; ++j)
#pragma unroll
            for (int q = 0; q < 4; ++q) acc[i][j][q] = 0.f;

    const int nch = K >> 5;

    ISSUE_STAGE(0, 0); CP_COMMIT();
    ISSUE_STAGE(1, 1); CP_COMMIT();

    int buf = 0;
    for (int c = 0; c < nch; ++c) {
        CP_WAITG(1);
        __syncthreads();
        if (c + 2 < nch) {
            int nb = buf + 2; if (nb >= 3) nb -= 3;
            ISSUE_STAGE(nb, c + 2);
        }
        CP_COMMIT();

        const uint32_t base = ((uint32_t)buf * STGB_) >> 2;
#pragma unroll
        for (int s = 0; s < 4; ++s) {
            const uint32_t ko = s * 8;
            uint32_t a[WMT][4], b[2][4];
#pragma unroll
            for (int mt = 0; mt < WMT; ++mt) {
                ldsm_x4(a[mt], sb + (base + fA + mt * (16 * RS3) + ko) * 4);
                if (RNDA) {
#pragma unroll
                    for (int q = 0; q < 4; ++q) a[mt][q] = tf32rb(a[mt][q]);
                }
            }
#pragma unroll
            for (int np = 0; np < 2; ++np)
                ldsm_x4(b[np], sb + (base + fB + np * (16 * RS3) + ko) * 4);
#pragma unroll
            for (int mt = 0; mt < WMT; ++mt)
#pragma unroll
                for (int nt = 0; nt < 4; ++nt) {
                    const int np = nt >> 1, e = (nt & 1) * 2;
                    mma_tf32(acc[mt][nt], a[mt][0], a[mt][1], a[mt][2], a[mt][3],
                             b[np][e], b[np][e + 1]);
                }
        }
        if (++buf == 3) buf = 0;
        __syncthreads();
    }
#undef ISSUE_STAGE

    const float* bp = (BIASMODE != 0) ? (bias + (long)blockIdx.z * sBias) : bias;
    float* Cp = C + (long)blockIdx.z * sC;
    const int row_base = m0 + wm * (16 * WMT);
    const int col_base = n0 + wn * 32;
    const int lr = lid >> 2, lc = (lid & 3) * 2;
#pragma unroll
    for (int mt = 0; mt < WMT; ++mt) {
        const int r0 = row_base + mt * 16 + lr;
#pragma unroll
        for (int nt = 0; nt < 4; ++nt) {
            const int cix = col_base + nt * 8 + lc;
            float b0 = 0.f, b1 = 0.f;
            if (BIASMODE == 1) { b0 = bp[cix]; b1 = bp[cix + 1]; }
            float v00 = acc[mt][nt][0] + b0, v01 = acc[mt][nt][1] + b1;
            float v10 = acc[mt][nt][2] + b0, v11 = acc[mt][nt][3] + b1;
            if (ROUND) {
                v00 = tf32r(v00); v01 = tf32r(v01);
                v10 = tf32r(v10); v11 = tf32r(v11);
            }
            *(float2*)(Cp + (long)r0 * ldc + cix)       = make_float2(v00, v01);
            *(float2*)(Cp + (long)(r0 + 8) * ldc + cix) = make_float2(v10, v11);
        }
    }
}

// ---------------------------------------------------------------------------
// Fused attention (unchanged from rounds 10-14).
// ---------------------------------------------------------------------------
__global__ __launch_bounds__(256, 1)
void attn_fused(const float* __restrict__ Q, const float* __restrict__ Km,
                const float* __restrict__ Vt, float* __restrict__ O)
{
    extern __shared__ char smem[];
    const uint32_t sb = smem_u32(smem);
    float* sf = (float*)smem;
    float* redmx = sf + AF_RED;
    float* redsm = redmx + 512;

    const int tid = threadIdx.x, wid = tid >> 5, lid = tid & 31;
    const int g4 = lid >> 2, t4 = lid & 3;
    const int lm = lid >> 3, lr8 = lid & 7;
    const int m0 = blockIdx.x * 64;
    const int z  = blockIdx.y;

    const float* Qg = Q + (long)z * HD + (long)m0 * C_DIM;
    const float* Kg = Km + (long)z * HD;
    const float* Vg = Vt + (long)z * HD * S_KV;

    const uint32_t aoffQ = (uint32_t)((lr8 + 8 * (lm & 1)) * QRS + 4 * (lm >> 1));
    const uint32_t boffK = (uint32_t)((lr8 + 8 * (lm >> 1)) * QRS + 4 * (lm & 1));
    const uint32_t aoffP = (uint32_t)((lr8 + 8 * (lm & 1)) * AF_PRS + 4 * (lm >> 1));
    const uint32_t boffV = (uint32_t)((lr8 + 8 * (lm >> 1)) * 68 + 4 * (lm & 1));

    {
#pragma unroll
        for (int i = 0; i < 8; ++i) {
            const int idx = i * 256 + tid;
            const int row = idx >> 5, ch = idx & 31;
            CP_ASYNC16(sb + (uint32_t)(row * QRS + ch * 4) * 4,
                       Qg + (long)row * C_DIM + ch * 4);
        }
#pragma unroll
        for (int i = 0; i < 16; ++i) {
            const int idx = i * 256 + tid;
            const int row = idx >> 5, ch = idx & 31;
            CP_ASYNC16(sb + (uint32_t)(AF_QW + row * QRS + ch * 4) * 4,
                       Kg + (long)row * C_DIM + ch * 4);
        }
        CP_COMMIT();
#pragma unroll
        for (int i = 0; i < 16; ++i) {
            const int idx = i * 256 + tid;
            const int row = idx >> 5, ch = idx & 31;
            CP_ASYNC16(sb + (uint32_t)(AF_QW + AF_KW + row * QRS + ch * 4) * 4,
                       Kg + (long)(128 + row) * C_DIM + ch * 4);
        }
        CP_COMMIT();
    }

    float acc[4][8][4];
#pragma unroll
    for (int i = 0; i < 4; ++i)
#pragma unroll
        for (int j = 0; j < 8; ++j)
#pragma unroll
            for (int q = 0; q < 4; ++q) acc[i][j][q] = 0.f;

#pragma unroll
    for (int c = 0; c < 4; ++c) {
        if (c < 3) { CP_WAITG(1); } else { CP_WAITG(0); }
        __syncthreads();

        const uint32_t kb = (uint32_t)(AF_QW + (c & 1) * AF_KW);
#pragma unroll
        for (int ks = 0; ks < 16; ++ks) {
            uint32_t a[4][4], b[4];
#pragma unroll
            for (int mt = 0; mt < 4; ++mt)
                ldsm_x4(a[mt], sb + (uint32_t)((16 * mt) * QRS + 8 * ks + aoffQ) * 4);
            ldsm_x4(b, sb + (kb + (uint32_t)((wid * 16) * QRS + 8 * ks) + boffK) * 4);
#pragma unroll
            for (int nt = 0; nt < 2; ++nt) {
                const uint32_t b0 = b[nt * 2], b1 = b[nt * 2 + 1];
#pragma unroll
                for (int mt = 0; mt < 4; ++mt)
                    mma_tf32(acc[mt][2 * c + nt],
                             a[mt][0], a[mt][1], a[mt][2], a[mt][3], b0, b1);
            }
        }
        __syncthreads();
        if (c + 2 < 4) {
            const uint32_t kb2 = (uint32_t)(AF_QW + (c & 1) * AF_KW);
#pragma unroll
            for (int i = 0; i < 16; ++i) {
                const int idx = i * 256 + tid;
                const int row = idx >> 5, ch = idx & 31;
                CP_ASYNC16(sb + (kb2 + (uint32_t)(row * QRS + ch * 4)) * 4,
                           Kg + (long)((c + 2) * 128 + row) * C_DIM + ch * 4);
            }
            CP_COMMIT();
        }
    }

#pragma unroll
    for (int b = 0; b < 2; ++b) {
#pragma unroll
        for (int i = 0; i < 8; ++i) {
            const int idx = i * 256 + tid;
            const int row = idx >> 4, ch = idx & 15;
            CP_ASYNC16(sb + (uint32_t)(b * AF_VW + row * 68 + ch * 4) * 4,
                       Vg + (long)row * S_KV + b * 64 + ch * 4);
        }
        CP_COMMIT();
    }

    float gm[4][2];
#pragma unroll
    for (int mt = 0; mt < 4; ++mt)
#pragma unroll
        for (int h = 0; h < 2; ++h) {
            float m = -1e30f;
#pragma unroll
            for (int j = 0; j < 8; ++j)
                m = fmaxf(m, fmaxf(acc[mt][j][2 * h], acc[mt][j][2 * h + 1]));
            m = fmaxf(m, __shfl_xor_sync(0xffffffffu, m, 1));
            m = fmaxf(m, __shfl_xor_sync(0xffffffffu, m, 2));
            if (t4 == 0) redmx[(16 * mt + 8 * h + g4) * 8 + wid] = m;
            gm[mt][h] = m;
        }
    __syncthreads();
#pragma unroll
    for (int mt = 0; mt < 4; ++mt)
#pragma unroll
        for (int h = 0; h < 2; ++h) {
            const int row = 16 * mt + 8 * h + g4;
            float m = gm[mt][h];
#pragma unroll
            for (int w = 0; w < 8; ++w) m = fmaxf(m, redmx[row * 8 + w]);
            gm[mt][h] = m;
        }
    float gs[4][2];
#pragma unroll
    for (int mt = 0; mt < 4; ++mt)
#pragma unroll
        for (int h = 0; h < 2; ++h) {
            float s = 0.f;
            const float m = gm[mt][h];
#pragma unroll
            for (int j = 0; j < 8; ++j) {
                float e0 = __expf(acc[mt][j][2 * h] - m);
                float e1 = __expf(acc[mt][j][2 * h + 1] - m);
                acc[mt][j][2 * h] = e0; acc[mt][j][2 * h + 1] = e1;
                s += e0 + e1;
            }
            s += __shfl_xor_sync(0xffffffffu, s, 1);
            s += __shfl_xor_sync(0xffffffffu, s, 2);
            if (t4 == 0) redsm[(16 * mt + 8 * h + g4) * 8 + wid] = s;
        }
    __syncthreads();
#pragma unroll
    for (int mt = 0; mt < 4; ++mt)
#pragma unroll
        for (int h = 0; h < 2; ++h) {
            const int row = 16 * mt + 8 * h + g4;
            float s = 0.f;
#pragma unroll
            for (int w = 0; w < 8; ++w) s += redsm[row * 8 + w];
            gs[mt][h] = 1.0f / s;
        }

#pragma unroll
    for (int mt = 0; mt < 4; ++mt)
#pragma unroll
        for (int h = 0; h < 2; ++h) {
            const int row = 16 * mt + 8 * h + g4;
            const float inv = gs[mt][h];
#pragma unroll
            for (int j = 0; j < 8; ++j) {
                const int col = 128 * (j >> 1) + wid * 16 + 8 * (j & 1) + 2 * t4;
                *(float2*)(sf + AF_PO + (uint32_t)(row * AF_PRS + col)) =
                    make_float2(tf32r(acc[mt][j][2 * h] * inv),
                                tf32r(acc[mt][j][2 * h + 1] * inv));
            }
        }
    __syncthreads();

    const int pwm = wid & 1, pwn = wid >> 1;
    float accP[2][4][4];
#pragma unroll
    for (int i = 0; i < 2; ++i)
#pragma unroll
        for (int j = 0; j < 4; ++j)
#pragma unroll
            for (int q = 0; q < 4; ++q) accP[i][j][q] = 0.f;

#pragma unroll
    for (int c = 0; c < 8; ++c) {
        if (c < 7) { CP_WAITG(1); } else { CP_WAITG(0); }
        __syncthreads();

        const uint32_t vb = (uint32_t)((c & 1) * AF_VW);
#pragma unroll
        for (int ks = 0; ks < 8; ++ks) {
            uint32_t a[2][4], b[2][4];
#pragma unroll
            for (int mt = 0; mt < 2; ++mt)
                ldsm_x4(a[mt], sb + (uint32_t)(AF_PO + (32 * pwm + 16 * mt) * AF_PRS
                                               + 64 * c + 8 * ks + aoffP) * 4);
#pragma unroll
            for (int np = 0; np < 2; ++np)
                ldsm_x4(b[np], sb + (vb + (uint32_t)((32 * pwn + 16 * np) * 68
                                                     + 8 * ks) + boffV) * 4);
#pragma unroll
            for (int nt = 0; nt < 4; ++nt) {
                const int np = nt >> 1, e = (nt & 1) * 2;
#pragma unroll
                for (int mt = 0; mt < 2; ++mt)
                    mma_tf32(accP[mt][nt],
                             a[mt][0], a[mt][1], a[mt][2], a[mt][3],
                             b[np][e], b[np][e + 1]);
            }
        }
        __syncthreads();
        if (c + 2 < 8) {
            const uint32_t vb2 = (uint32_t)((c & 1) * AF_VW);
#pragma unroll
            for (int i = 0; i < 8; ++i) {
                const int idx = i * 256 + tid;
                const int row = idx >> 4, ch = idx & 15;
                CP_ASYNC16(sb + (vb2 + (uint32_t)(row * 68 + ch * 4)) * 4,
                           Vg + (long)row * S_KV + (c + 2) * 64 + ch * 4);
            }
            CP_COMMIT();
        }
    }

    float* Og = O + (long)m0 * C_DIM + (long)z * HD;
    const int lr = lid >> 2, lc = (lid & 3) * 2;
#pragma unroll
    for (int mt = 0; mt < 2; ++mt) {
        const int r0 = 32 * pwm + 16 * mt + lr;
#pragma unroll
        for (int nt = 0; nt < 4; ++nt) {
            const int cix = 32 * pwn + 8 * nt + lc;
            *(float2*)(Og + (long)r0 * C_DIM + cix) =
                make_float2(tf32r(accP[mt][nt][0]), tf32r(accP[mt][nt][1]));
            *(float2*)(Og + (long)(r0 + 8) * C_DIM + cix) =
                make_float2(tf32r(accP[mt][nt][2]), tf32r(accP[mt][nt][3]));
        }
    }
}

// ---------------------------------------------------------------------------
// elementwise helpers (unchanged)
// ---------------------------------------------------------------------------
__device__ __forceinline__ void transT_body(const float* __restrict__ W,
                                            float* __restrict__ out,
                                            int Kd, int Nd, int bx, int by,
                                            int tidx)
{
    __shared__ float t[32][33];
    const int k0 = by * 32, n0 = bx * 32;
    const int tx = tidx & 31, ty = tidx >> 5;
#pragma unroll
    for (int r = 0; r < 4; ++r)
        t[ty + 8 * r][tx] = W[(long)(k0 + ty + 8 * r) * Nd + n0 + tx];
    __syncthreads();
#pragma unroll
    for (int r = 0; r < 4; ++r)
        out[(long)(n0 + ty + 8 * r) * Kd + k0 + tx] = tf32r(t[tx][ty + 8 * r]);
}

__global__ __launch_bounds__(256)
void transT4_kernel(const float* __restrict__ Wq, const float* __restrict__ Wk,
                    const float* __restrict__ Wv, const float* __restrict__ Wo,
                    float* __restrict__ wqt, float* __restrict__ wkvt,
                    float* __restrict__ wot)
{
    const int by = blockIdx.y;
    if (by < 64)
        transT_body(Wq, wqt, C_DIM, C_DIM, blockIdx.x, by, threadIdx.x);
    else if (by < 192)
        transT_body(Wk, wkvt, CTXD, C_DIM, blockIdx.x, by - 64, threadIdx.x);
    else if (by < 320)
        transT_body(Wv, wkvt + (long)C_DIM * CTXD, CTXD, C_DIM,
                    blockIdx.x, by - 192, threadIdx.x);
    else
        transT_body(Wo, wot, C_DIM, C_DIM, blockIdx.x, by - 320, threadIdx.x);
}

__global__ __launch_bounds__(256)
void transT_kernel(const float* __restrict__ W, float* __restrict__ out,
                   int Kd, int Nd)
{
    transT_body(W, out, Kd, Nd, blockIdx.x, blockIdx.y, threadIdx.x);
}

__global__ void concat_bias_kernel(const float* __restrict__ bk,
                                   const float* __restrict__ bv,
                                   float* __restrict__ o)
{
    int i = blockIdx.x * 256 + threadIdx.x;
    o[i] = bk[i];
    o[C_DIM + i] = bv[i];
}

__global__ __launch_bounds__(256)
void rmsnorm_kernel(float* __restrict__ buf, const float* __restrict__ g, float scale)
{
    float* row = buf + (long)blockIdx.x * C_DIM;
    const int t = threadIdx.x;
    float4 v0 = *(float4*)(row + t * 4);
    float4 v1 = *(float4*)(row + 1024 + t * 4);
    float ss = v0.x * v0.x + v0.y * v0.y + v0.z * v0.z + v0.w * v0.w
             + v1.x * v1.x + v1.y * v1.y + v1.z * v1.z + v1.w * v1.w;
#pragma unroll
    for (int o = 16; o > 0; o >>= 1) ss += __shfl_xor_sync(0xffffffffu, ss, o);
    __shared__ float ws[8]; __shared__ float s_inv;
    if ((t & 31) == 0) ws[t >> 5] = ss;
    __syncthreads();
    if (t == 0) {
        float s = 0.f;
#pragma unroll
        for (int i = 0; i < 8; ++i) s += ws[i];
        s_inv = rsqrtf(s * (1.0f / C_DIM) + 1e-6f) * scale;
    }
    __syncthreads();
    const float inv = s_inv;
    float4 w0 = *(const float4*)(g + t * 4);
    float4 w1 = *(const float4*)(g + 1024 + t * 4);
    *(float4*)(row + t * 4) = make_float4(
        tf32r(v0.x * inv * w0.x), tf32r(v0.y * inv * w0.y),
        tf32r(v0.z * inv * w0.z), tf32r(v0.w * inv * w0.w));
    *(float4*)(row + 1024 + t * 4) = make_float4(
        tf32r(v1.x * inv * w1.x), tf32r(v1.y * inv * w1.y),
        tf32r(v1.z * inv * w1.z), tf32r(v1.w * inv * w1.w));
}

// ---------------------------------------------------------------------------
extern "C" void kernel_launch(void* const* d_in, const int* in_sizes, int n_in,
                              void* d_out, int out_size)
{
    (void)in_sizes; (void)n_in; (void)out_size;
    const float* x   = (const float*)d_in[0];
    const float* ctx = (const float*)d_in[1];
    const float* Wq  = (const float*)d_in[2];
    const float* bq  = (const float*)d_in[3];
    const float* Wk  = (const float*)d_in[4];
    const float* bk  = (const float*)d_in[5];
    const float* Wv  = (const float*)d_in[6];
    const float* bv  = (const float*)d_in[7];
    const float* Wo  = (const float*)d_in[8];
    const float* bo  = (const float*)d_in[9];
    const float* gq  = (const float*)d_in[10];
    const float* gk  = (const float*)d_in[11];
    float* out = (float*)d_out;

    cudaFuncSetAttribute(tf_gemm<1,0,1,4>, cudaFuncAttributeMaxDynamicSharedMemorySize,
                         SMEMSZ(4));
    cudaFuncSetAttribute(tf_gemm<1,0,1,2>, cudaFuncAttributeMaxDynamicSharedMemorySize,
                         SMEMSZ(2));
    cudaFuncSetAttribute(tf_gemm<1,0,0,4>, cudaFuncAttributeMaxDynamicSharedMemorySize,
                         SMEMSZ(4));
    cudaFuncSetAttribute(attn_fused, cudaFuncAttributeMaxDynamicSharedMemorySize, AF_SMB);

    float *wqt, *wkvt, *wot, *qf, *kvf, *vt, *atf, *bkv;
    cudaGetSymbolAddress((void**)&wqt,  g_wqt);
    cudaGetSymbolAddress((void**)&wkvt, g_wkvt);
    cudaGetSymbolAddress((void**)&wot,  g_wot);
    cudaGetSymbolAddress((void**)&qf,   g_qf);
    cudaGetSymbolAddress((void**)&kvf,  g_kvf);
    cudaGetSymbolAddress((void**)&vt,   g_vt);
    cudaGetSymbolAddress((void**)&atf,  g_atf);
    cudaGetSymbolAddress((void**)&bkv,  g_bkv);

    const long WKV = (long)C_DIM * CTXD;
    const long SKV = (long)S_KV * C_DIM;
    const float ATTN_SCALE = 0.08838834764831845f;   // 1/sqrt(128)

    // ---- weight transposes (merged) + bias concat --------------------------
    transT4_kernel<<<dim3(64, 384), 256>>>(Wq, Wk, Wv, Wo, wqt, wkvt, wot);
    concat_bias_kernel<<<C_DIM / 256, 256>>>(bk, bv, bkv);

    // ---- projections --------------------------------------------------------
    // q = x @ Wq + bq      (128x128 tiles, 1024 CTAs, 2/SM)
    tf_gemm<1,0,1,4><<<dim3(16, 64, 1), 256, SMEMSZ(4)>>>(
        x, C_DIM, 0, wqt, C_DIM, 0, bq, 0, qf, C_DIM, 0, C_DIM);
    // [k|v] = ctx @ [Wk|Wv] + [bk|bv]   (64x128 tiles, 256 CTAs, 2/SM)
    tf_gemm<1,0,1,2><<<dim3(16, 8, 2), 256, SMEMSZ(2)>>>(
        ctx, CTXD, 0, wkvt, CTXD, WKV, bkv, C_DIM, kvf, C_DIM, SKV, CTXD);

    // ---- norms / transposes -------------------------------------------------
    rmsnorm_kernel<<<L_Q, 256>>>(qf, gq, ATTN_SCALE);
    rmsnorm_kernel<<<S_KV, 256>>>(kvf, gk, 1.0f);
    transT_kernel<<<dim3(C_DIM / 32, S_KV / 32), 256>>>(kvf + SKV, vt, S_KV, C_DIM);

    // ---- fused attention ----------------------------------------------------
    attn_fused<<<dim3(L_Q / 64, NH), 256, AF_SMB>>>(qf, kvf, vt, atf);

    // ---- output projection --------------------------------------------------
    tf_gemm<1,0,0,4><<<dim3(16, 64, 1), 256, SMEMSZ(4)>>>(
        atf, C_DIM, 0, wot, C_DIM, 0, bo, 0, out, C_DIM, 0, C_DIM);
}

// round 16
// speedup vs baseline: 1.0001x; 1.0001x over previous
#include <cuda_runtime.h>
#include <cstdint>
#include <math.h>

// ===========================================================================
// WanCrossAttention  (B=1, L=8192, S=512, C=2048, CTX=4096, H=16, D=128)
// Round-16: TF32 pipeline; tf_gemm gains NSTG (pipeline depth) template:
//   KV projection -> WMT=2, NSTG=4 (3 chunks in flight; R15 showed KV is
//   DRAM-latency-exposed, invariant to occupancy).
//   Q/O projections stay WMT=4, NSTG=3 (2 CTAs/SM smem limit).
// Arithmetic bit-identical to rounds 9-15.
// ===========================================================================

#define L_Q   8192
#define S_KV  512
#define C_DIM 2048
#define CTXD  4096
#define NH    16
#define HD    128

// tf32 GEMM tiling: TK=32 fp32
#define RS3   36                     // smem row stride (words): 32 + 4 pad
#define RS3B  144
#define BT3   (128 * RS3B)           // B tile bytes (N=128 always)
#define SMEMSZ(WMT, NSTG) ((NSTG) * ((WMT) * 32 * RS3B + BT3))
// WMT=4,NSTG=3: 110592 B ; WMT=2,NSTG=4: 110592 B  -> both 2 CTAs/SM

// attn_fused smem layout (unchanged)
#define QRS    132
#define AF_QW  (64 * QRS)
#define AF_KW  (128 * QRS)
#define AF_VW  (128 * 68)
#define AF_PO  17408
#define AF_PRS 516
#define AF_RED 50432
#define AF_SMW 51456
#define AF_SMB (AF_SMW * 4)          // 205824 B

// ---------------- scratch ---------------------------------------------------
__device__ float g_wqt[C_DIM * C_DIM];
__device__ float g_wkvt[2 * C_DIM * CTXD];
__device__ float g_wot[C_DIM * C_DIM];
__device__ float g_qf[L_Q * C_DIM];
__device__ float g_kvf[2 * S_KV * C_DIM];
__device__ float g_vt[C_DIM * S_KV];
__device__ float g_atf[L_Q * C_DIM];
__device__ float g_bkv[2 * C_DIM];

// ---------------- asm helpers ----------------------------------------------
__device__ __forceinline__ uint32_t smem_u32(const void* p) {
    uint32_t a;
    asm("{ .reg .u64 t; cvta.to.shared.u64 t, %1; cvt.u32.u64 %0, t; }"
        : "=r"(a) : "l"(p));
    return a;
}
__device__ __forceinline__ float tf32r(float x) {
    uint32_t o;
    asm("cvt.rna.tf32.f32 %0, %1;" : "=r"(o) : "f"(x));
    return __uint_as_float(o);
}
__device__ __forceinline__ uint32_t tf32rb(uint32_t x) {
    uint32_t o;
    asm("cvt.rna.tf32.f32 %0, %1;" : "=r"(o) : "f"(__uint_as_float(x)));
    return o;
}
__device__ __forceinline__ void ldsm_x4(uint32_t* r, uint32_t addr) {
    asm volatile("ldmatrix.sync.aligned.m8n8.x4.shared.b16 {%0,%1,%2,%3}, [%4];"
                 : "=r"(r[0]), "=r"(r[1]), "=r"(r[2]), "=r"(r[3]) : "r"(addr));
}
__device__ __forceinline__ void mma_tf32(float* c, uint32_t a0, uint32_t a1,
                                         uint32_t a2, uint32_t a3,
                                         uint32_t b0, uint32_t b1) {
    asm volatile(
        "mma.sync.aligned.m16n8k8.row.col.f32.tf32.tf32.f32 "
        "{%0,%1,%2,%3}, {%4,%5,%6,%7}, {%8,%9}, {%0,%1,%2,%3};"
        : "+f"(c[0]), "+f"(c[1]), "+f"(c[2]), "+f"(c[3])
        : "r"(a0), "r"(a1), "r"(a2), "r"(a3), "r"(b0), "r"(b1));
}
#define CP_ASYNC16(dst, src) \
    asm volatile("cp.async.cg.shared.global [%0], [%1], 16;" :: "r"(dst), "l"(src))
#define CP_COMMIT() asm volatile("cp.async.commit_group;" ::: "memory")
#define CP_WAITG(n) asm volatile("cp.async.wait_group %0;" :: "n"(n) : "memory")

// ---------------------------------------------------------------------------
// TF32 GEMM, K-chunk 32, NSTG-stage pipeline, 2 CTAs/SM.
// WMT = m16 tiles per warp (4 -> CTA 128xN, 2 -> CTA 64xN). N tile = 128.
// K % 32 == 0, K/32 >= NSTG-1.
// ---------------------------------------------------------------------------
template <int BIASMODE, int ROUND, int RNDA, int WMT, int NSTG>
__global__ __launch_bounds__(256, 2)
void tf_gemm(const float* __restrict__ A, int lda, long sA,
             const float* __restrict__ B, int ldb, long sB,
             const float* __restrict__ bias, long sBias,
             float* __restrict__ C, int ldc, long sC, int K)
{
    constexpr int CM   = WMT * 32;
    constexpr uint32_t ATB = (uint32_t)CM * RS3B;
    constexpr uint32_t STGB_ = ATB + BT3;
    constexpr int NA = CM / 32;

    extern __shared__ char smem[];
    const uint32_t sb = smem_u32(smem);
    const int tid = threadIdx.x, wid = tid >> 5, lid = tid & 31;
    const int m0 = blockIdx.y * CM, n0 = blockIdx.x * 128;

    const float* Ab = A + (long)blockIdx.z * sA + (long)m0 * lda;
    const float* Bb = B + (long)blockIdx.z * sB + (long)n0 * ldb;

    uint32_t goffA[NA], soA[NA], goffB[4], soB[4];
#pragma unroll
    for (int i = 0; i < NA; ++i) {
        const int idx = i * 256 + tid;
        const int row = (idx >> 3) & (CM - 1);
        const int ch  = idx & 7;
        goffA[i] = (uint32_t)(row * lda + ch * 4);
        soA[i] = (uint32_t)(row * RS3B + ch * 16);
    }
#pragma unroll
    for (int i = 0; i < 4; ++i) {
        const int idx = i * 256 + tid;
        const int row = (idx >> 3) & 127;
        const int ch  = idx & 7;
        goffB[i] = (uint32_t)(row * ldb + ch * 4);
        soB[i] = (uint32_t)(ATB + row * RS3B + ch * 16);
    }

#define ISSUE_STAGE(stage, kidx) do {                                       \
        const uint32_t _db = sb + (uint32_t)(stage) * STGB_;                \
        const uint32_t _go = (uint32_t)(kidx) * 32;                         \
        _Pragma("unroll")                                                   \
        for (int _i = 0; _i < NA; ++_i)                                     \
            CP_ASYNC16(_db + soA[_i], Ab + goffA[_i] + _go);                \
        _Pragma("unroll")                                                   \
        for (int _i = 0; _i < 4; ++_i)                                      \
            CP_ASYNC16(_db + soB[_i], Bb + goffB[_i] + _go);                \
    } while (0)

    const int lm = lid >> 3, lr8 = lid & 7;
    const int wm = wid >> 2, wn = wid & 3;
    const uint32_t fA = (uint32_t)((wm * (16 * WMT) + lr8 + 8 * (lm & 1)) * RS3
                                   + 4 * (lm >> 1));
    const uint32_t fB = (uint32_t)(ATB / 4 + (wn * 32 + lr8 + 8 * (lm >> 1)) * RS3
                                   + 4 * (lm & 1));

    float acc[WMT][4][4];
#pragma unroll
    for (int i = 0; i < WMT; ++i)
#pragma unroll
        for (int j = 0; j < 4; ++j)
#pragma unroll
            for (int q = 0; q < 4; ++q) acc[i][j][q] = 0.f;

    const int nch = K >> 5;

#pragma unroll
    for (int s = 0; s < NSTG - 1; ++s) { ISSUE_STAGE(s, s); CP_COMMIT(); }

    int buf = 0;
    for (int c = 0; c < nch; ++c) {
        CP_WAITG(NSTG - 2);
        __syncthreads();
        if (c + NSTG - 1 < nch) {
            int nb = buf + NSTG - 1; if (nb >= NSTG) nb -= NSTG;
            ISSUE_STAGE(nb, c + NSTG - 1);
        }
        CP_COMMIT();

        const uint32_t base = ((uint32_t)buf * STGB_) >> 2;
#pragma unroll
        for (int s = 0; s < 4; ++s) {
            const uint32_t ko = s * 8;
            uint32_t a[WMT][4], b[2][4];
#pragma unroll
            for (int mt = 0; mt < WMT; ++mt) {
                ldsm_x4(a[mt], sb + (base + fA + mt * (16 * RS3) + ko) * 4);
                if (RNDA) {
#pragma unroll
                    for (int q = 0; q < 4; ++q) a[mt][q] = tf32rb(a[mt][q]);
                }
            }
#pragma unroll
            for (int np = 0; np < 2; ++np)
                ldsm_x4(b[np], sb + (base + fB + np * (16 * RS3) + ko) * 4);
#pragma unroll
            for (int mt = 0; mt < WMT; ++mt)
#pragma unroll
                for (int nt = 0; nt < 4; ++nt) {
                    const int np = nt >> 1, e = (nt & 1) * 2;
                    mma_tf32(acc[mt][nt], a[mt][0], a[mt][1], a[mt][2], a[mt][3],
                             b[np][e], b[np][e + 1]);
                }
        }
        if (++buf == NSTG) buf = 0;
        __syncthreads();
    }
#undef ISSUE_STAGE

    const float* bp = (BIASMODE != 0) ? (bias + (long)blockIdx.z * sBias) : bias;
    float* Cp = C + (long)blockIdx.z * sC;
    const int row_base = m0 + wm * (16 * WMT);
    const int col_base = n0 + wn * 32;
    const int lr = lid >> 2, lc = (lid & 3) * 2;
#pragma unroll
    for (int mt = 0; mt < WMT; ++mt) {
        const int r0 = row_base + mt * 16 + lr;
#pragma unroll
        for (int nt = 0; nt < 4; ++nt) {
            const int cix = col_base + nt * 8 + lc;
            float b0 = 0.f, b1 = 0.f;
            if (BIASMODE == 1) { b0 = bp[cix]; b1 = bp[cix + 1]; }
            float v00 = acc[mt][nt][0] + b0, v01 = acc[mt][nt][1] + b1;
            float v10 = acc[mt][nt][2] + b0, v11 = acc[mt][nt][3] + b1;
            if (ROUND) {
                v00 = tf32r(v00); v01 = tf32r(v01);
                v10 = tf32r(v10); v11 = tf32r(v11);
            }
            *(float2*)(Cp + (long)r0 * ldc + cix)       = make_float2(v00, v01);
            *(float2*)(Cp + (long)(r0 + 8) * ldc + cix) = make_float2(v10, v11);
        }
    }
}

// ---------------------------------------------------------------------------
// Fused attention (unchanged from rounds 10-15).
// ---------------------------------------------------------------------------
__global__ __launch_bounds__(256, 1)
void attn_fused(const float* __restrict__ Q, const float* __restrict__ Km,
                const float* __restrict__ Vt, float* __restrict__ O)
{
    extern __shared__ char smem[];
    const uint32_t sb = smem_u32(smem);
    float* sf = (float*)smem;
    float* redmx = sf + AF_RED;
    float* redsm = redmx + 512;

    const int tid = threadIdx.x, wid = tid >> 5, lid = tid & 31;
    const int g4 = lid >> 2, t4 = lid & 3;
    const int lm = lid >> 3, lr8 = lid & 7;
    const int m0 = blockIdx.x * 64;
    const int z  = blockIdx.y;

    const float* Qg = Q + (long)z * HD + (long)m0 * C_DIM;
    const float* Kg = Km + (long)z * HD;
    const float* Vg = Vt + (long)z * HD * S_KV;

    const uint32_t aoffQ = (uint32_t)((lr8 + 8 * (lm & 1)) * QRS + 4 * (lm >> 1));
    const uint32_t boffK = (uint32_t)((lr8 + 8 * (lm >> 1)) * QRS + 4 * (lm & 1));
    const uint32_t aoffP = (uint32_t)((lr8 + 8 * (lm & 1)) * AF_PRS + 4 * (lm >> 1));
    const uint32_t boffV = (uint32_t)((lr8 + 8 * (lm >> 1)) * 68 + 4 * (lm & 1));

    {
#pragma unroll
        for (int i = 0; i < 8; ++i) {
            const int idx = i * 256 + tid;
            const int row = idx >> 5, ch = idx & 31;
            CP_ASYNC16(sb + (uint32_t)(row * QRS + ch * 4) * 4,
                       Qg + (long)row * C_DIM + ch * 4);
        }
#pragma unroll
        for (int i = 0; i < 16; ++i) {
            const int idx = i * 256 + tid;
            const int row = idx >> 5, ch = idx & 31;
            CP_ASYNC16(sb + (uint32_t)(AF_QW + row * QRS + ch * 4) * 4,
                       Kg + (long)row * C_DIM + ch * 4);
        }
        CP_COMMIT();
#pragma unroll
        for (int i = 0; i < 16; ++i) {
            const int idx = i * 256 + tid;
            const int row = idx >> 5, ch = idx & 31;
            CP_ASYNC16(sb + (uint32_t)(AF_QW + AF_KW + row * QRS + ch * 4) * 4,
                       Kg + (long)(128 + row) * C_DIM + ch * 4);
        }
        CP_COMMIT();
    }

    float acc[4][8][4];
#pragma unroll
    for (int i = 0; i < 4; ++i)
#pragma unroll
        for (int j = 0; j < 8; ++j)
#pragma unroll
            for (int q = 0; q < 4; ++q) acc[i][j][q] = 0.f;

#pragma unroll
    for (int c = 0; c < 4; ++c) {
        if (c < 3) { CP_WAITG(1); } else { CP_WAITG(0); }
        __syncthreads();

        const uint32_t kb = (uint32_t)(AF_QW + (c & 1) * AF_KW);
#pragma unroll
        for (int ks = 0; ks < 16; ++ks) {
            uint32_t a[4][4], b[4];
#pragma unroll
            for (int mt = 0; mt < 4; ++mt)
                ldsm_x4(a[mt], sb + (uint32_t)((16 * mt) * QRS + 8 * ks + aoffQ) * 4);
            ldsm_x4(b, sb + (kb + (uint32_t)((wid * 16) * QRS + 8 * ks) + boffK) * 4);
#pragma unroll
            for (int nt = 0; nt < 2; ++nt) {
                const uint32_t b0 = b[nt * 2], b1 = b[nt * 2 + 1];
#pragma unroll
                for (int mt = 0; mt < 4; ++mt)
                    mma_tf32(acc[mt][2 * c + nt],
                             a[mt][0], a[mt][1], a[mt][2], a[mt][3], b0, b1);
            }
        }
        __syncthreads();
        if (c + 2 < 4) {
            const uint32_t kb2 = (uint32_t)(AF_QW + (c & 1) * AF_KW);
#pragma unroll
            for (int i = 0; i < 16; ++i) {
                const int idx = i * 256 + tid;
                const int row = idx >> 5, ch = idx & 31;
                CP_ASYNC16(sb + (kb2 + (uint32_t)(row * QRS + ch * 4)) * 4,
                           Kg + (long)((c + 2) * 128 + row) * C_DIM + ch * 4);
            }
            CP_COMMIT();
        }
    }

#pragma unroll
    for (int b = 0; b < 2; ++b) {
#pragma unroll
        for (int i = 0; i < 8; ++i) {
            const int idx = i * 256 + tid;
            const int row = idx >> 4, ch = idx & 15;
            CP_ASYNC16(sb + (uint32_t)(b * AF_VW + row * 68 + ch * 4) * 4,
                       Vg + (long)row * S_KV + b * 64 + ch * 4);
        }
        CP_COMMIT();
    }

    float gm[4][2];
#pragma unroll
    for (int mt = 0; mt < 4; ++mt)
#pragma unroll
        for (int h = 0; h < 2; ++h) {
            float m = -1e30f;
#pragma unroll
            for (int j = 0; j < 8; ++j)
                m = fmaxf(m, fmaxf(acc[mt][j][2 * h], acc[mt][j][2 * h + 1]));
            m = fmaxf(m, __shfl_xor_sync(0xffffffffu, m, 1));
            m = fmaxf(m, __shfl_xor_sync(0xffffffffu, m, 2));
            if (t4 == 0) redmx[(16 * mt + 8 * h + g4) * 8 + wid] = m;
            gm[mt][h] = m;
        }
    __syncthreads();
#pragma unroll
    for (int mt = 0; mt < 4; ++mt)
#pragma unroll
        for (int h = 0; h < 2; ++h) {
            const int row = 16 * mt + 8 * h + g4;
            float m = gm[mt][h];
#pragma unroll
            for (int w = 0; w < 8; ++w) m = fmaxf(m, redmx[row * 8 + w]);
            gm[mt][h] = m;
        }
    float gs[4][2];
#pragma unroll
    for (int mt = 0; mt < 4; ++mt)
#pragma unroll
        for (int h = 0; h < 2; ++h) {
            float s = 0.f;
            const float m = gm[mt][h];
#pragma unroll
            for (int j = 0; j < 8; ++j) {
                float e0 = __expf(acc[mt][j][2 * h] - m);
                float e1 = __expf(acc[mt][j][2 * h + 1] - m);
                acc[mt][j][2 * h] = e0; acc[mt][j][2 * h + 1] = e1;
                s += e0 + e1;
            }
            s += __shfl_xor_sync(0xffffffffu, s, 1);
            s += __shfl_xor_sync(0xffffffffu, s, 2);
            if (t4 == 0) redsm[(16 * mt + 8 * h + g4) * 8 + wid] = s;
        }
    __syncthreads();
#pragma unroll
    for (int mt = 0; mt < 4; ++mt)
#pragma unroll
        for (int h = 0; h < 2; ++h) {
            const int row = 16 * mt + 8 * h + g4;
            float s = 0.f;
#pragma unroll
            for (int w = 0; w < 8; ++w) s += redsm[row * 8 + w];
            gs[mt][h] = 1.0f / s;
        }

#pragma unroll
    for (int mt = 0; mt < 4; ++mt)
#pragma unroll
        for (int h = 0; h < 2; ++h) {
            const int row = 16 * mt + 8 * h + g4;
            const float inv = gs[mt][h];
#pragma unroll
            for (int j = 0; j < 8; ++j) {
                const int col = 128 * (j >> 1) + wid * 16 + 8 * (j & 1) + 2 * t4;
                *(float2*)(sf + AF_PO + (uint32_t)(row * AF_PRS + col)) =
                    make_float2(tf32r(acc[mt][j][2 * h] * inv),
                                tf32r(acc[mt][j][2 * h + 1] * inv));
            }
        }
    __syncthreads();

    const int pwm = wid & 1, pwn = wid >> 1;
    float accP[2][4][4];
#pragma unroll
    for (int i = 0; i < 2; ++i)
#pragma unroll
        for (int j = 0; j < 4; ++j)
#pragma unroll
            for (int q = 0; q < 4; ++q) accP[i][j][q] = 0.f;

#pragma unroll
    for (int c = 0; c < 8; ++c) {
        if (c < 7) { CP_WAITG(1); } else { CP_WAITG(0); }
        __syncthreads();

        const uint32_t vb = (uint32_t)((c & 1) * AF_VW);
#pragma unroll
        for (int ks = 0; ks < 8; ++ks) {
            uint32_t a[2][4], b[2][4];
#pragma unroll
            for (int mt = 0; mt < 2; ++mt)
                ldsm_x4(a[mt], sb + (uint32_t)(AF_PO + (32 * pwm + 16 * mt) * AF_PRS
                                               + 64 * c + 8 * ks + aoffP) * 4);
#pragma unroll
            for (int np = 0; np < 2; ++np)
                ldsm_x4(b[np], sb + (vb + (uint32_t)((32 * pwn + 16 * np) * 68
                                                     + 8 * ks) + boffV) * 4);
#pragma unroll
            for (int nt = 0; nt < 4; ++nt) {
                const int np = nt >> 1, e = (nt & 1) * 2;
#pragma unroll
                for (int mt = 0; mt < 2; ++mt)
                    mma_tf32(accP[mt][nt],
                             a[mt][0], a[mt][1], a[mt][2], a[mt][3],
                             b[np][e], b[np][e + 1]);
            }
        }
        __syncthreads();
        if (c + 2 < 8) {
            const uint32_t vb2 = (uint32_t)((c & 1) * AF_VW);
#pragma unroll
            for (int i = 0; i < 8; ++i) {
                const int idx = i * 256 + tid;
                const int row = idx >> 4, ch = idx & 15;
                CP_ASYNC16(sb + (vb2 + (uint32_t)(row * 68 + ch * 4)) * 4,
                           Vg + (long)row * S_KV + (c + 2) * 64 + ch * 4);
            }
            CP_COMMIT();
        }
    }

    float* Og = O + (long)m0 * C_DIM + (long)z * HD;
    const int lr = lid >> 2, lc = (lid & 3) * 2;
#pragma unroll
    for (int mt = 0; mt < 2; ++mt) {
        const int r0 = 32 * pwm + 16 * mt + lr;
#pragma unroll
        for (int nt = 0; nt < 4; ++nt) {
            const int cix = 32 * pwn + 8 * nt + lc;
            *(float2*)(Og + (long)r0 * C_DIM + cix) =
                make_float2(tf32r(accP[mt][nt][0]), tf32r(accP[mt][nt][1]));
            *(float2*)(Og + (long)(r0 + 8) * C_DIM + cix) =
                make_float2(tf32r(accP[mt][nt][2]), tf32r(accP[mt][nt][3]));
        }
    }
}

// ---------------------------------------------------------------------------
// elementwise helpers (unchanged)
// ---------------------------------------------------------------------------
__device__ __forceinline__ void transT_body(const float* __restrict__ W,
                                            float* __restrict__ out,
                                            int Kd, int Nd, int bx, int by,
                                            int tidx)
{
    __shared__ float t[32][33];
    const int k0 = by * 32, n0 = bx * 32;
    const int tx = tidx & 31, ty = tidx >> 5;
#pragma unroll
    for (int r = 0; r < 4; ++r)
        t[ty + 8 * r][tx] = W[(long)(k0 + ty + 8 * r) * Nd + n0 + tx];
    __syncthreads();
#pragma unroll
    for (int r = 0; r < 4; ++r)
        out[(long)(n0 + ty + 8 * r) * Kd + k0 + tx] = tf32r(t[tx][ty + 8 * r]);
}

__global__ __launch_bounds__(256)
void transT4_kernel(const float* __restrict__ Wq, const float* __restrict__ Wk,
                    const float* __restrict__ Wv, const float* __restrict__ Wo,
                    float* __restrict__ wqt, float* __restrict__ wkvt,
                    float* __restrict__ wot)
{
    const int by = blockIdx.y;
    if (by < 64)
        transT_body(Wq, wqt, C_DIM, C_DIM, blockIdx.x, by, threadIdx.x);
    else if (by < 192)
        transT_body(Wk, wkvt, CTXD, C_DIM, blockIdx.x, by - 64, threadIdx.x);
    else if (by < 320)
        transT_body(Wv, wkvt + (long)C_DIM * CTXD, CTXD, C_DIM,
                    blockIdx.x, by - 192, threadIdx.x);
    else
        transT_body(Wo, wot, C_DIM, C_DIM, blockIdx.x, by - 320, threadIdx.x);
}

__global__ __launch_bounds__(256)
void transT_kernel(const float* __restrict__ W, float* __restrict__ out,
                   int Kd, int Nd)
{
    transT_body(W, out, Kd, Nd, blockIdx.x, blockIdx.y, threadIdx.x);
}

__global__ void concat_bias_kernel(const float* __restrict__ bk,
                                   const float* __restrict__ bv,
                                   float* __restrict__ o)
{
    int i = blockIdx.x * 256 + threadIdx.x;
    o[i] = bk[i];
    o[C_DIM + i] = bv[i];
}

__global__ __launch_bounds__(256)
void rmsnorm_kernel(float* __restrict__ buf, const float* __restrict__ g, float scale)
{
    float* row = buf + (long)blockIdx.x * C_DIM;
    const int t = threadIdx.x;
    float4 v0 = *(float4*)(row + t * 4);
    float4 v1 = *(float4*)(row + 1024 + t * 4);
    float ss = v0.x * v0.x + v0.y * v0.y + v0.z * v0.z + v0.w * v0.w
             + v1.x * v1.x + v1.y * v1.y + v1.z * v1.z + v1.w * v1.w;
#pragma unroll
    for (int o = 16; o > 0; o >>= 1) ss += __shfl_xor_sync(0xffffffffu, ss, o);
    __shared__ float ws[8]; __shared__ float s_inv;
    if ((t & 31) == 0) ws[t >> 5] = ss;
    __syncthreads();
    if (t == 0) {
        float s = 0.f;
#pragma unroll
        for (int i = 0; i < 8; ++i) s += ws[i];
        s_inv = rsqrtf(s * (1.0f / C_DIM) + 1e-6f) * scale;
    }
    __syncthreads();
    const float inv = s_inv;
    float4 w0 = *(const float4*)(g + t * 4);
    float4 w1 = *(const float4*)(g + 1024 + t * 4);
    *(float4*)(row + t * 4) = make_float4(
        tf32r(v0.x * inv * w0.x), tf32r(v0.y * inv * w0.y),
        tf32r(v0.z * inv * w0.z), tf32r(v0.w * inv * w0.w));
    *(float4*)(row + 1024 + t * 4) = make_float4(
        tf32r(v1.x * inv * w1.x), tf32r(v1.y * inv * w1.y),
        tf32r(v1.z * inv * w1.z), tf32r(v1.w * inv * w1.w));
}

// ---------------------------------------------------------------------------
extern "C" void kernel_launch(void* const* d_in, const int* in_sizes, int n_in,
                              void* d_out, int out_size)
{
    (void)in_sizes; (void)n_in; (void)out_size;
    const float* x   = (const float*)d_in[0];
    const float* ctx = (const float*)d_in[1];
    const float* Wq  = (const float*)d_in[2];
    const float* bq  = (const float*)d_in[3];
    const float* Wk  = (const float*)d_in[4];
    const float* bk  = (const float*)d_in[5];
    const float* Wv  = (const float*)d_in[6];
    const float* bv  = (const float*)d_in[7];
    const float* Wo  = (const float*)d_in[8];
    const float* bo  = (const float*)d_in[9];
    const float* gq  = (const float*)d_in[10];
    const float* gk  = (const float*)d_in[11];
    float* out = (float*)d_out;

    cudaFuncSetAttribute(tf_gemm<1,0,1,4,3>, cudaFuncAttributeMaxDynamicSharedMemorySize,
                         SMEMSZ(4, 3));
    cudaFuncSetAttribute(tf_gemm<1,0,1,2,4>, cudaFuncAttributeMaxDynamicSharedMemorySize,
                         SMEMSZ(2, 4));
    cudaFuncSetAttribute(tf_gemm<1,0,0,4,3>, cudaFuncAttributeMaxDynamicSharedMemorySize,
                         SMEMSZ(4, 3));
    cudaFuncSetAttribute(attn_fused, cudaFuncAttributeMaxDynamicSharedMemorySize, AF_SMB);

    float *wqt, *wkvt, *wot, *qf, *kvf, *vt, *atf, *bkv;
    cudaGetSymbolAddress((void**)&wqt,  g_wqt);
    cudaGetSymbolAddress((void**)&wkvt, g_wkvt);
    cudaGetSymbolAddress((void**)&wot,  g_wot);
    cudaGetSymbolAddress((void**)&qf,   g_qf);
    cudaGetSymbolAddress((void**)&kvf,  g_kvf);
    cudaGetSymbolAddress((void**)&vt,   g_vt);
    cudaGetSymbolAddress((void**)&atf,  g_atf);
    cudaGetSymbolAddress((void**)&bkv,  g_bkv);

    const long WKV = (long)C_DIM * CTXD;
    const long SKV = (long)S_KV * C_DIM;
    const float ATTN_SCALE = 0.08838834764831845f;   // 1/sqrt(128)

    // ---- weight transposes (merged) + bias concat --------------------------
    transT4_kernel<<<dim3(64, 384), 256>>>(Wq, Wk, Wv, Wo, wqt, wkvt, wot);
    concat_bias_kernel<<<C_DIM / 256, 256>>>(bk, bv, bkv);

    // ---- projections --------------------------------------------------------
    // q = x @ Wq + bq      (128x128 tiles, 1024 CTAs, 2/SM, 3 stages)
    tf_gemm<1,0,1,4,3><<<dim3(16, 64, 1), 256, SMEMSZ(4, 3)>>>(
        x, C_DIM, 0, wqt, C_DIM, 0, bq, 0, qf, C_DIM, 0, C_DIM);
    // [k|v] = ctx @ [Wk|Wv] + [bk|bv]  (64x128 tiles, 256 CTAs, 2/SM, 4 stages)
    tf_gemm<1,0,1,2,4><<<dim3(16, 8, 2), 256, SMEMSZ(2, 4)>>>(
        ctx, CTXD, 0, wkvt, CTXD, WKV, bkv, C_DIM, kvf, C_DIM, SKV, CTXD);

    // ---- norms / transposes -------------------------------------------------
    rmsnorm_kernel<<<L_Q, 256>>>(qf, gq, ATTN_SCALE);
    rmsnorm_kernel<<<S_KV, 256>>>(kvf, gk, 1.0f);
    transT_kernel<<<dim3(C_DIM / 32, S_KV / 32), 256>>>(kvf + SKV, vt, S_KV, C_DIM);

    // ---- fused attention ----------------------------------------------------
    attn_fused<<<dim3(L_Q / 64, NH), 256, AF_SMB>>>(qf, kvf, vt, atf);

    // ---- output projection --------------------------------------------------
    tf_gemm<1,0,0,4,3><<<dim3(16, 64, 1), 256, SMEMSZ(4, 3)>>>(
        atf, C_DIM, 0, wot, C_DIM, 0, bo, 0, out, C_DIM, 0, C_DIM);
}

// round 17
// speedup vs baseline: 1.0140x; 1.0139x over previous
#include <cuda_runtime.h>
#include <cstdint>
#include <math.h>

// ===========================================================================
// WanCrossAttention  (B=1, L=8192, S=512, C=2048, CTX=4096, H=16, D=128)
// Round-17: identical kernels to Round 16; kernel_launch forks the graph:
//   KV chain (KV-proj, rmsnorm(kv), transT(vt)) runs on a second stream,
//   overlapped with the Q chain (Q-proj, rmsnorm(q)). Joined before attn.
//   All GEMMs measure ~42% tensor / ~31% issue -> co-scheduling fills holes.
// Arithmetic bit-identical to rounds 9-16.
// ===========================================================================

#define L_Q   8192
#define S_KV  512
#define C_DIM 2048
#define CTXD  4096
#define NH    16
#define HD    128

#define RS3   36
#define RS3B  144
#define BT3   (128 * RS3B)
#define SMEMSZ(WMT, NSTG) ((NSTG) * ((WMT) * 32 * RS3B + BT3))

#define QRS    132
#define AF_QW  (64 * QRS)
#define AF_KW  (128 * QRS)
#define AF_VW  (128 * 68)
#define AF_PO  17408
#define AF_PRS 516
#define AF_RED 50432
#define AF_SMW 51456
#define AF_SMB (AF_SMW * 4)

// ---------------- scratch ---------------------------------------------------
__device__ float g_wqt[C_DIM * C_DIM];
__device__ float g_wkvt[2 * C_DIM * CTXD];
__device__ float g_wot[C_DIM * C_DIM];
__device__ float g_qf[L_Q * C_DIM];
__device__ float g_kvf[2 * S_KV * C_DIM];
__device__ float g_vt[C_DIM * S_KV];
__device__ float g_atf[L_Q * C_DIM];
__device__ float g_bkv[2 * C_DIM];

// ---------------- asm helpers ----------------------------------------------
__device__ __forceinline__ uint32_t smem_u32(const void* p) {
    uint32_t a;
    asm("{ .reg .u64 t; cvta.to.shared.u64 t, %1; cvt.u32.u64 %0, t; }"
        : "=r"(a) : "l"(p));
    return a;
}
__device__ __forceinline__ float tf32r(float x) {
    uint32_t o;
    asm("cvt.rna.tf32.f32 %0, %1;" : "=r"(o) : "f"(x));
    return __uint_as_float(o);
}
__device__ __forceinline__ uint32_t tf32rb(uint32_t x) {
    uint32_t o;
    asm("cvt.rna.tf32.f32 %0, %1;" : "=r"(o) : "f"(__uint_as_float(x)));
    return o;
}
__device__ __forceinline__ void ldsm_x4(uint32_t* r, uint32_t addr) {
    asm volatile("ldmatrix.sync.aligned.m8n8.x4.shared.b16 {%0,%1,%2,%3}, [%4];"
                 : "=r"(r[0]), "=r"(r[1]), "=r"(r[2]), "=r"(r[3]) : "r"(addr));
}
__device__ __forceinline__ void mma_tf32(float* c, uint32_t a0, uint32_t a1,
                                         uint32_t a2, uint32_t a3,
                                         uint32_t b0, uint32_t b1) {
    asm volatile(
        "mma.sync.aligned.m16n8k8.row.col.f32.tf32.tf32.f32 "
        "{%0,%1,%2,%3}, {%4,%5,%6,%7}, {%8,%9}, {%0,%1,%2,%3};"
        : "+f"(c[0]), "+f"(c[1]), "+f"(c[2]), "+f"(c[3])
        : "r"(a0), "r"(a1), "r"(a2), "r"(a3), "r"(b0), "r"(b1));
}
#define CP_ASYNC16(dst, src) \
    asm volatile("cp.async.cg.shared.global [%0], [%1], 16;" :: "r"(dst), "l"(src))
#define CP_COMMIT() asm volatile("cp.async.commit_group;" ::: "memory")
#define CP_WAITG(n) asm volatile("cp.async.wait_group %0;" :: "n"(n) : "memory")

// ---------------------------------------------------------------------------
// TF32 GEMM, K-chunk 32, NSTG-stage pipeline, 2 CTAs/SM. (unchanged R16)
// ---------------------------------------------------------------------------
template <int BIASMODE, int ROUND, int RNDA, int WMT, int NSTG>
__global__ __launch_bounds__(256, 2)
void tf_gemm(const float* __restrict__ A, int lda, long sA,
             const float* __restrict__ B, int ldb, long sB,
             const float* __restrict__ bias, long sBias,
             float* __restrict__ C, int ldc, long sC, int K)
{
    constexpr int CM   = WMT * 32;
    constexpr uint32_t ATB = (uint32_t)CM * RS3B;
    constexpr uint32_t STGB_ = ATB + BT3;
    constexpr int NA = CM / 32;

    extern __shared__ char smem[];
    const uint32_t sb = smem_u32(smem);
    const int tid = threadIdx.x, wid = tid >> 5, lid = tid & 31;
    const int m0 = blockIdx.y * CM, n0 = blockIdx.x * 128;

    const float* Ab = A + (long)blockIdx.z * sA + (long)m0 * lda;
    const float* Bb = B + (long)blockIdx.z * sB + (long)n0 * ldb;

    uint32_t goffA[NA], soA[NA], goffB[4], soB[4];
#pragma unroll
    for (int i = 0; i < NA; ++i) {
        const int idx = i * 256 + tid;
        const int row = (idx >> 3) & (CM - 1);
        const int ch  = idx & 7;
        goffA[i] = (uint32_t)(row * lda + ch * 4);
        soA[i] = (uint32_t)(row * RS3B + ch * 16);
    }
#pragma unroll
    for (int i = 0; i < 4; ++i) {
        const int idx = i * 256 + tid;
        const int row = (idx >> 3) & 127;
        const int ch  = idx & 7;
        goffB[i] = (uint32_t)(row * ldb + ch * 4);
        soB[i] = (uint32_t)(ATB + row * RS3B + ch * 16);
    }

#define ISSUE_STAGE(stage, kidx) do {                                       \
        const uint32_t _db = sb + (uint32_t)(stage) * STGB_;                \
        const uint32_t _go = (uint32_t)(kidx) * 32;                         \
        _Pragma("unroll")                                                   \
        for (int _i = 0; _i < NA; ++_i)                                     \
            CP_ASYNC16(_db + soA[_i], Ab + goffA[_i] + _go);                \
        _Pragma("unroll")                                                   \
        for (int _i = 0; _i < 4; ++_i)                                      \
            CP_ASYNC16(_db + soB[_i], Bb + goffB[_i] + _go);                \
    } while (0)

    const int lm = lid >> 3, lr8 = lid & 7;
    const int wm = wid >> 2, wn = wid & 3;
    const uint32_t fA = (uint32_t)((wm * (16 * WMT) + lr8 + 8 * (lm & 1)) * RS3
                                   + 4 * (lm >> 1));
    const uint32_t fB = (uint32_t)(ATB / 4 + (wn * 32 + lr8 + 8 * (lm >> 1)) * RS3
                                   + 4 * (lm & 1));

    float acc[WMT][4][4];
#pragma unroll
    for (int i = 0; i < WMT; ++i)
#pragma unroll
        for (int j = 0; j < 4; ++j)
#pragma unroll
            for (int q = 0; q < 4; ++q) acc[i][j][q] = 0.f;

    const int nch = K >> 5;

#pragma unroll
    for (int s = 0; s < NSTG - 1; ++s) { ISSUE_STAGE(s, s); CP_COMMIT(); }

    int buf = 0;
    for (int c = 0; c < nch; ++c) {
        CP_WAITG(NSTG - 2);
        __syncthreads();
        if (c + NSTG - 1 < nch) {
            int nb = buf + NSTG - 1; if (nb >= NSTG) nb -= NSTG;
            ISSUE_STAGE(nb, c + NSTG - 1);
        }
        CP_COMMIT();

        const uint32_t base = ((uint32_t)buf * STGB_) >> 2;
#pragma unroll
        for (int s = 0; s < 4; ++s) {
            const uint32_t ko = s * 8;
            uint32_t a[WMT][4], b[2][4];
#pragma unroll
            for (int mt = 0; mt < WMT; ++mt) {
                ldsm_x4(a[mt], sb + (base + fA + mt * (16 * RS3) + ko) * 4);
                if (RNDA) {
#pragma unroll
                    for (int q = 0; q < 4; ++q) a[mt][q] = tf32rb(a[mt][q]);
                }
            }
#pragma unroll
            for (int np = 0; np < 2; ++np)
                ldsm_x4(b[np], sb + (base + fB + np * (16 * RS3) + ko) * 4);
#pragma unroll
            for (int mt = 0; mt < WMT; ++mt)
#pragma unroll
                for (int nt = 0; nt < 4; ++nt) {
                    const int np = nt >> 1, e = (nt & 1) * 2;
                    mma_tf32(acc[mt][nt], a[mt][0], a[mt][1], a[mt][2], a[mt][3],
                             b[np][e], b[np][e + 1]);
                }
        }
        if (++buf == NSTG) buf = 0;
        __syncthreads();
    }
#undef ISSUE_STAGE

    const float* bp = (BIASMODE != 0) ? (bias + (long)blockIdx.z * sBias) : bias;
    float* Cp = C + (long)blockIdx.z * sC;
    const int row_base = m0 + wm * (16 * WMT);
    const int col_base = n0 + wn * 32;
    const int lr = lid >> 2, lc = (lid & 3) * 2;
#pragma unroll
    for (int mt = 0; mt < WMT; ++mt) {
        const int r0 = row_base + mt * 16 + lr;
#pragma unroll
        for (int nt = 0; nt < 4; ++nt) {
            const int cix = col_base + nt * 8 + lc;
            float b0 = 0.f, b1 = 0.f;
            if (BIASMODE == 1) { b0 = bp[cix]; b1 = bp[cix + 1]; }
            float v00 = acc[mt][nt][0] + b0, v01 = acc[mt][nt][1] + b1;
            float v10 = acc[mt][nt][2] + b0, v11 = acc[mt][nt][3] + b1;
            if (ROUND) {
                v00 = tf32r(v00); v01 = tf32r(v01);
                v10 = tf32r(v10); v11 = tf32r(v11);
            }
            *(float2*)(Cp + (long)r0 * ldc + cix)       = make_float2(v00, v01);
            *(float2*)(Cp + (long)(r0 + 8) * ldc + cix) = make_float2(v10, v11);
        }
    }
}

// ---------------------------------------------------------------------------
// Fused attention (unchanged from rounds 10-16).
// ---------------------------------------------------------------------------
__global__ __launch_bounds__(256, 1)
void attn_fused(const float* __restrict__ Q, const float* __restrict__ Km,
                const float* __restrict__ Vt, float* __restrict__ O)
{
    extern __shared__ char smem[];
    const uint32_t sb = smem_u32(smem);
    float* sf = (float*)smem;
    float* redmx = sf + AF_RED;
    float* redsm = redmx + 512;

    const int tid = threadIdx.x, wid = tid >> 5, lid = tid & 31;
    const int g4 = lid >> 2, t4 = lid & 3;
    const int lm = lid >> 3, lr8 = lid & 7;
    const int m0 = blockIdx.x * 64;
    const int z  = blockIdx.y;

    const float* Qg = Q + (long)z * HD + (long)m0 * C_DIM;
    const float* Kg = Km + (long)z * HD;
    const float* Vg = Vt + (long)z * HD * S_KV;

    const uint32_t aoffQ = (uint32_t)((lr8 + 8 * (lm & 1)) * QRS + 4 * (lm >> 1));
    const uint32_t boffK = (uint32_t)((lr8 + 8 * (lm >> 1)) * QRS + 4 * (lm & 1));
    const uint32_t aoffP = (uint32_t)((lr8 + 8 * (lm & 1)) * AF_PRS + 4 * (lm >> 1));
    const uint32_t boffV = (uint32_t)((lr8 + 8 * (lm >> 1)) * 68 + 4 * (lm & 1));

    {
#pragma unroll
        for (int i = 0; i < 8; ++i) {
            const int idx = i * 256 + tid;
            const int row = idx >> 5, ch = idx & 31;
            CP_ASYNC16(sb + (uint32_t)(row * QRS + ch * 4) * 4,
                       Qg + (long)row * C_DIM + ch * 4);
        }
#pragma unroll
        for (int i = 0; i < 16; ++i) {
            const int idx = i * 256 + tid;
            const int row = idx >> 5, ch = idx & 31;
            CP_ASYNC16(sb + (uint32_t)(AF_QW + row * QRS + ch * 4) * 4,
                       Kg + (long)row * C_DIM + ch * 4);
        }
        CP_COMMIT();
#pragma unroll
        for (int i = 0; i < 16; ++i) {
            const int idx = i * 256 + tid;
            const int row = idx >> 5, ch = idx & 31;
            CP_ASYNC16(sb + (uint32_t)(AF_QW + AF_KW + row * QRS + ch * 4) * 4,
                       Kg + (long)(128 + row) * C_DIM + ch * 4);
        }
        CP_COMMIT();
    }

    float acc[4][8][4];
#pragma unroll
    for (int i = 0; i < 4; ++i)
#pragma unroll
        for (int j = 0; j < 8; ++j)
#pragma unroll
            for (int q = 0; q < 4; ++q) acc[i][j][q] = 0.f;

#pragma unroll
    for (int c = 0; c < 4; ++c) {
        if (c < 3) { CP_WAITG(1); } else { CP_WAITG(0); }
        __syncthreads();

        const uint32_t kb = (uint32_t)(AF_QW + (c & 1) * AF_KW);
#pragma unroll
        for (int ks = 0; ks < 16; ++ks) {
            uint32_t a[4][4], b[4];
#pragma unroll
            for (int mt = 0; mt < 4; ++mt)
                ldsm_x4(a[mt], sb + (uint32_t)((16 * mt) * QRS + 8 * ks + aoffQ) * 4);
            ldsm_x4(b, sb + (kb + (uint32_t)((wid * 16) * QRS + 8 * ks) + boffK) * 4);
#pragma unroll
            for (int nt = 0; nt < 2; ++nt) {
                const uint32_t b0 = b[nt * 2], b1 = b[nt * 2 + 1];
#pragma unroll
                for (int mt = 0; mt < 4; ++mt)
                    mma_tf32(acc[mt][2 * c + nt],
                             a[mt][0], a[mt][1], a[mt][2], a[mt][3], b0, b1);
            }
        }
        __syncthreads();
        if (c + 2 < 4) {
            const uint32_t kb2 = (uint32_t)(AF_QW + (c & 1) * AF_KW);
#pragma unroll
            for (int i = 0; i < 16; ++i) {
                const int idx = i * 256 + tid;
                const int row = idx >> 5, ch = idx & 31;
                CP_ASYNC16(sb + (kb2 + (uint32_t)(row * QRS + ch * 4)) * 4,
                           Kg + (long)((c + 2) * 128 + row) * C_DIM + ch * 4);
            }
            CP_COMMIT();
        }
    }

#pragma unroll
    for (int b = 0; b < 2; ++b) {
#pragma unroll
        for (int i = 0; i < 8; ++i) {
            const int idx = i * 256 + tid;
            const int row = idx >> 4, ch = idx & 15;
            CP_ASYNC16(sb + (uint32_t)(b * AF_VW + row * 68 + ch * 4) * 4,
                       Vg + (long)row * S_KV + b * 64 + ch * 4);
        }
        CP_COMMIT();
    }

    float gm[4][2];
#pragma unroll
    for (int mt = 0; mt < 4; ++mt)
#pragma unroll
        for (int h = 0; h < 2; ++h) {
            float m = -1e30f;
#pragma unroll
            for (int j = 0; j < 8; ++j)
                m = fmaxf(m, fmaxf(acc[mt][j][2 * h], acc[mt][j][2 * h + 1]));
            m = fmaxf(m, __shfl_xor_sync(0xffffffffu, m, 1));
            m = fmaxf(m, __shfl_xor_sync(0xffffffffu, m, 2));
            if (t4 == 0) redmx[(16 * mt + 8 * h + g4) * 8 + wid] = m;
            gm[mt][h] = m;
        }
    __syncthreads();
#pragma unroll
    for (int mt = 0; mt < 4; ++mt)
#pragma unroll
        for (int h = 0; h < 2; ++h) {
            const int row = 16 * mt + 8 * h + g4;
            float m = gm[mt][h];
#pragma unroll
            for (int w = 0; w < 8; ++w) m = fmaxf(m, redmx[row * 8 + w]);
            gm[mt][h] = m;
        }
    float gs[4][2];
#pragma unroll
    for (int mt = 0; mt < 4; ++mt)
#pragma unroll
        for (int h = 0; h < 2; ++h) {
            float s = 0.f;
            const float m = gm[mt][h];
#pragma unroll
            for (int j = 0; j < 8; ++j) {
                float e0 = __expf(acc[mt][j][2 * h] - m);
                float e1 = __expf(acc[mt][j][2 * h + 1] - m);
                acc[mt][j][2 * h] = e0; acc[mt][j][2 * h + 1] = e1;
                s += e0 + e1;
            }
            s += __shfl_xor_sync(0xffffffffu, s, 1);
            s += __shfl_xor_sync(0xffffffffu, s, 2);
            if (t4 == 0) redsm[(16 * mt + 8 * h + g4) * 8 + wid] = s;
        }
    __syncthreads();
#pragma unroll
    for (int mt = 0; mt < 4; ++mt)
#pragma unroll
        for (int h = 0; h < 2; ++h) {
            const int row = 16 * mt + 8 * h + g4;
            float s = 0.f;
#pragma unroll
            for (int w = 0; w < 8; ++w) s += redsm[row * 8 + w];
            gs[mt][h] = 1.0f / s;
        }

#pragma unroll
    for (int mt = 0; mt < 4; ++mt)
#pragma unroll
        for (int h = 0; h < 2; ++h) {
            const int row = 16 * mt + 8 * h + g4;
            const float inv = gs[mt][h];
#pragma unroll
            for (int j = 0; j < 8; ++j) {
                const int col = 128 * (j >> 1) + wid * 16 + 8 * (j & 1) + 2 * t4;
                *(float2*)(sf + AF_PO + (uint32_t)(row * AF_PRS + col)) =
                    make_float2(tf32r(acc[mt][j][2 * h] * inv),
                                tf32r(acc[mt][j][2 * h + 1] * inv));
            }
        }
    __syncthreads();

    const int pwm = wid & 1, pwn = wid >> 1;
    float accP[2][4][4];
#pragma unroll
    for (int i = 0; i < 2; ++i)
#pragma unroll
        for (int j = 0; j < 4; ++j)
#pragma unroll
            for (int q = 0; q < 4; ++q) accP[i][j][q] = 0.f;

#pragma unroll
    for (int c = 0; c < 8; ++c) {
        if (c < 7) { CP_WAITG(1); } else { CP_WAITG(0); }
        __syncthreads();

        const uint32_t vb = (uint32_t)((c & 1) * AF_VW);
#pragma unroll
        for (int ks = 0; ks < 8; ++ks) {
            uint32_t a[2][4], b[2][4];
#pragma unroll
            for (int mt = 0; mt < 2; ++mt)
                ldsm_x4(a[mt], sb + (uint32_t)(AF_PO + (32 * pwm + 16 * mt) * AF_PRS
                                               + 64 * c + 8 * ks + aoffP) * 4);
#pragma unroll
            for (int np = 0; np < 2; ++np)
                ldsm_x4(b[np], sb + (vb + (uint32_t)((32 * pwn + 16 * np) * 68
                                                     + 8 * ks) + boffV) * 4);
#pragma unroll
            for (int nt = 0; nt < 4; ++nt) {
                const int np = nt >> 1, e = (nt & 1) * 2;
#pragma unroll
                for (int mt = 0; mt < 2; ++mt)
                    mma_tf32(accP[mt][nt],
                             a[mt][0], a[mt][1], a[mt][2], a[mt][3],
                             b[np][e], b[np][e + 1]);
            }
        }
        __syncthreads();
        if (c + 2 < 8) {
            const uint32_t vb2 = (uint32_t)((c & 1) * AF_VW);
#pragma unroll
            for (int i = 0; i < 8; ++i) {
                const int idx = i * 256 + tid;
                const int row = idx >> 4, ch = idx & 15;
                CP_ASYNC16(sb + (vb2 + (uint32_t)(row * 68 + ch * 4)) * 4,
                           Vg + (long)row * S_KV + (c + 2) * 64 + ch * 4);
            }
            CP_COMMIT();
        }
    }

    float* Og = O + (long)m0 * C_DIM + (long)z * HD;
    const int lr = lid >> 2, lc = (lid & 3) * 2;
#pragma unroll
    for (int mt = 0; mt < 2; ++mt) {
        const int r0 = 32 * pwm + 16 * mt + lr;
#pragma unroll
        for (int nt = 0; nt < 4; ++nt) {
            const int cix = 32 * pwn + 8 * nt + lc;
            *(float2*)(Og + (long)r0 * C_DIM + cix) =
                make_float2(tf32r(accP[mt][nt][0]), tf32r(accP[mt][nt][1]));
            *(float2*)(Og + (long)(r0 + 8) * C_DIM + cix) =
                make_float2(tf32r(accP[mt][nt][2]), tf32r(accP[mt][nt][3]));
        }
    }
}

// ---------------------------------------------------------------------------
// elementwise helpers (unchanged)
// ---------------------------------------------------------------------------
__device__ __forceinline__ void transT_body(const float* __restrict__ W,
                                            float* __restrict__ out,
                                            int Kd, int Nd, int bx, int by,
                                            int tidx)
{
    __shared__ float t[32][33];
    const int k0 = by * 32, n0 = bx * 32;
    const int tx = tidx & 31, ty = tidx >> 5;
#pragma unroll
    for (int r = 0; r < 4; ++r)
        t[ty + 8 * r][tx] = W[(long)(k0 + ty + 8 * r) * Nd + n0 + tx];
    __syncthreads();
#pragma unroll
    for (int r = 0; r < 4; ++r)
        out[(long)(n0 + ty + 8 * r) * Kd + k0 + tx] = tf32r(t[tx][ty + 8 * r]);
}

__global__ __launch_bounds__(256)
void transT4_kernel(const float* __restrict__ Wq, const float* __restrict__ Wk,
                    const float* __restrict__ Wv, const float* __restrict__ Wo,
                    float* __restrict__ wqt, float* __restrict__ wkvt,
                    float* __restrict__ wot)
{
    const int by = blockIdx.y;
    if (by < 64)
        transT_body(Wq, wqt, C_DIM, C_DIM, blockIdx.x, by, threadIdx.x);
    else if (by < 192)
        transT_body(Wk, wkvt, CTXD, C_DIM, blockIdx.x, by - 64, threadIdx.x);
    else if (by < 320)
        transT_body(Wv, wkvt + (long)C_DIM * CTXD, CTXD, C_DIM,
                    blockIdx.x, by - 192, threadIdx.x);
    else
        transT_body(Wo, wot, C_DIM, C_DIM, blockIdx.x, by - 320, threadIdx.x);
}

__global__ __launch_bounds__(256)
void transT_kernel(const float* __restrict__ W, float* __restrict__ out,
                   int Kd, int Nd)
{
    transT_body(W, out, Kd, Nd, blockIdx.x, blockIdx.y, threadIdx.x);
}

__global__ void concat_bias_kernel(const float* __restrict__ bk,
                                   const float* __restrict__ bv,
                                   float* __restrict__ o)
{
    int i = blockIdx.x * 256 + threadIdx.x;
    o[i] = bk[i];
    o[C_DIM + i] = bv[i];
}

__global__ __launch_bounds__(256)
void rmsnorm_kernel(float* __restrict__ buf, const float* __restrict__ g, float scale)
{
    float* row = buf + (long)blockIdx.x * C_DIM;
    const int t = threadIdx.x;
    float4 v0 = *(float4*)(row + t * 4);
    float4 v1 = *(float4*)(row + 1024 + t * 4);
    float ss = v0.x * v0.x + v0.y * v0.y + v0.z * v0.z + v0.w * v0.w
             + v1.x * v1.x + v1.y * v1.y + v1.z * v1.z + v1.w * v1.w;
#pragma unroll
    for (int o = 16; o > 0; o >>= 1) ss += __shfl_xor_sync(0xffffffffu, ss, o);
    __shared__ float ws[8]; __shared__ float s_inv;
    if ((t & 31) == 0) ws[t >> 5] = ss;
    __syncthreads();
    if (t == 0) {
        float s = 0.f;
#pragma unroll
        for (int i = 0; i < 8; ++i) s += ws[i];
        s_inv = rsqrtf(s * (1.0f / C_DIM) + 1e-6f) * scale;
    }
    __syncthreads();
    const float inv = s_inv;
    float4 w0 = *(const float4*)(g + t * 4);
    float4 w1 = *(const float4*)(g + 1024 + t * 4);
    *(float4*)(row + t * 4) = make_float4(
        tf32r(v0.x * inv * w0.x), tf32r(v0.y * inv * w0.y),
        tf32r(v0.z * inv * w0.z), tf32r(v0.w * inv * w0.w));
    *(float4*)(row + 1024 + t * 4) = make_float4(
        tf32r(v1.x * inv * w1.x), tf32r(v1.y * inv * w1.y),
        tf32r(v1.z * inv * w1.z), tf32r(v1.w * inv * w1.w));
}

// ---------------------------------------------------------------------------
extern "C" void kernel_launch(void* const* d_in, const int* in_sizes, int n_in,
                              void* d_out, int out_size)
{
    (void)in_sizes; (void)n_in; (void)out_size;
    const float* x   = (const float*)d_in[0];
    const float* ctx = (const float*)d_in[1];
    const float* Wq  = (const float*)d_in[2];
    const float* bq  = (const float*)d_in[3];
    const float* Wk  = (const float*)d_in[4];
    const float* bk  = (const float*)d_in[5];
    const float* Wv  = (const float*)d_in[6];
    const float* bv  = (const float*)d_in[7];
    const float* Wo  = (const float*)d_in[8];
    const float* bo  = (const float*)d_in[9];
    const float* gq  = (const float*)d_in[10];
    const float* gk  = (const float*)d_in[11];
    float* out = (float*)d_out;

    // second stream + fork/join events (created once, outside capture; the
    // harness's first call is the uncaptured correctness run)
    static cudaStream_t s2 = nullptr;
    static cudaEvent_t evFork = nullptr, evJoin = nullptr;
    if (s2 == nullptr) {
        cudaStreamCreateWithFlags(&s2, cudaStreamNonBlocking);
        cudaEventCreateWithFlags(&evFork, cudaEventDisableTiming);
        cudaEventCreateWithFlags(&evJoin, cudaEventDisableTiming);
    }

    cudaFuncSetAttribute(tf_gemm<1,0,1,4,3>, cudaFuncAttributeMaxDynamicSharedMemorySize,
                         SMEMSZ(4, 3));
    cudaFuncSetAttribute(tf_gemm<1,0,1,2,4>, cudaFuncAttributeMaxDynamicSharedMemorySize,
                         SMEMSZ(2, 4));
    cudaFuncSetAttribute(tf_gemm<1,0,0,4,3>, cudaFuncAttributeMaxDynamicSharedMemorySize,
                         SMEMSZ(4, 3));
    cudaFuncSetAttribute(attn_fused, cudaFuncAttributeMaxDynamicSharedMemorySize, AF_SMB);

    float *wqt, *wkvt, *wot, *qf, *kvf, *vt, *atf, *bkv;
    cudaGetSymbolAddress((void**)&wqt,  g_wqt);
    cudaGetSymbolAddress((void**)&wkvt, g_wkvt);
    cudaGetSymbolAddress((void**)&wot,  g_wot);
    cudaGetSymbolAddress((void**)&qf,   g_qf);
    cudaGetSymbolAddress((void**)&kvf,  g_kvf);
    cudaGetSymbolAddress((void**)&vt,   g_vt);
    cudaGetSymbolAddress((void**)&atf,  g_atf);
    cudaGetSymbolAddress((void**)&bkv,  g_bkv);

    const long WKV = (long)C_DIM * CTXD;
    const long SKV = (long)S_KV * C_DIM;
    const float ATTN_SCALE = 0.08838834764831845f;   // 1/sqrt(128)

    // ---- common prologue (default stream) ----------------------------------
    transT4_kernel<<<dim3(64, 384), 256>>>(Wq, Wk, Wv, Wo, wqt, wkvt, wot);
    concat_bias_kernel<<<C_DIM / 256, 256>>>(bk, bv, bkv);
    cudaEventRecord(evFork, 0);

    // ---- KV chain on s2 (independent of Q chain) ---------------------------
    cudaStreamWaitEvent(s2, evFork, 0);
    tf_gemm<1,0,1,2,4><<<dim3(16, 8, 2), 256, SMEMSZ(2, 4), s2>>>(
        ctx, CTXD, 0, wkvt, CTXD, WKV, bkv, C_DIM, kvf, C_DIM, SKV, CTXD);
    rmsnorm_kernel<<<S_KV, 256, 0, s2>>>(kvf, gk, 1.0f);
    transT_kernel<<<dim3(C_DIM / 32, S_KV / 32), 256, 0, s2>>>(
        kvf + SKV, vt, S_KV, C_DIM);
    cudaEventRecord(evJoin, s2);

    // ---- Q chain on default stream (overlapped with KV chain) --------------
    tf_gemm<1,0,1,4,3><<<dim3(16, 64, 1), 256, SMEMSZ(4, 3)>>>(
        x, C_DIM, 0, wqt, C_DIM, 0, bq, 0, qf, C_DIM, 0, C_DIM);
    rmsnorm_kernel<<<L_Q, 256>>>(qf, gq, ATTN_SCALE);

    // ---- join, then attention + output projection --------------------------
    cudaStreamWaitEvent(0, evJoin, 0);
    attn_fused<<<dim3(L_Q / 64, NH), 256, AF_SMB>>>(qf, kvf, vt, atf);
    tf_gemm<1,0,0,4,3><<<dim3(16, 64, 1), 256, SMEMSZ(4, 3)>>>(
        atf, C_DIM, 0, wot, C_DIM, 0, bo, 0, out, C_DIM, 0, C_DIM);
}